// round 5
// baseline (speedup 1.0000x reference)
#include <cuda_runtime.h>
#include <cuda_fp16.h>
#include <cstdint>

#define NPAT 50000
#define NCON 20000
#define NN   70000
#define EE   800000
#define HH   128
#define LL   2

// ---------------- scratch (static device globals; no allocs allowed) ----------------
__device__ float  g_buf0[(size_t)NN * HH];
__device__ float  g_buf1[(size_t)NN * HH];
__device__ float  g_agg [(size_t)NN * HH];
__device__ __half g_h0  [(size_t)NN * HH];   // fp16 copy of layer inputs (for gather)
__device__ __half g_h1  [(size_t)NN * HH];
__device__ int    g_deg [NN];
__device__ float  g_rcnt[NN];
__device__ int    g_off [NN + 1];
__device__ int    g_cur [NN];
__device__ int    g_csr [2 * EE];
// fragment-permuted tf32-split weights:
//  [0 .. 262144)   : 4 layer variants x 8 chunks x 8192 floats
//  [262144..278528): W_p  (2 chunks)
//  [278528..311296): W_c  (4 chunks)
__device__ float g_B[311296];

#define B_LAYER_V   65536
#define B_CHUNK     8192
#define B_WP_OFF    262144
#define B_WC_OFF    278528

// ---------------- helpers ----------------
__device__ __forceinline__ float cvt_tf32(float v) {
    float h; asm("cvt.rna.tf32.f32 %0, %1;" : "=f"(h) : "f"(v)); return h;
}
__device__ __forceinline__ void mma_tf32(float* c, const uint32_t* a, const uint32_t* b) {
    asm volatile(
        "mma.sync.aligned.m16n8k8.row.col.f32.tf32.tf32.f32 "
        "{%0,%1,%2,%3}, {%4,%5,%6,%7}, {%8,%9}, {%0,%1,%2,%3};"
        : "+f"(c[0]), "+f"(c[1]), "+f"(c[2]), "+f"(c[3])
        : "r"(a[0]), "r"(a[1]), "r"(a[2]), "r"(a[3]),
          "r"(b[0]), "r"(b[1]));
}

// ---------------- smem layout (floats) ----------------
#define ASTR   36
#define SM_AHI 0
#define SM_ALO 4608
#define SM_BP  9216
#define SM_FLOATS (9216 + 8192)       // 17408 floats = 69632 B

// ---------------- per-chunk mma core: 4 k8-steps over a 32-deep chunk ---------------
__device__ __forceinline__ void chunk_mma(const float* sm, int warpM, int warpN, int lane,
                                          float acc[2][8][4]) {
    int gid = lane >> 2, tig = lane & 3;
#pragma unroll
    for (int k8 = 0; k8 < 4; k8++) {
        uint32_t ah[2][4], al[2][4];
#pragma unroll
        for (int mt = 0; mt < 2; mt++) {
            int r0 = warpM * 32 + mt * 16 + gid;
            int c0 = k8 * 8 + tig;
            ah[mt][0] = __float_as_uint(sm[SM_AHI + r0 * ASTR + c0]);
            ah[mt][1] = __float_as_uint(sm[SM_AHI + (r0 + 8) * ASTR + c0]);
            ah[mt][2] = __float_as_uint(sm[SM_AHI + r0 * ASTR + c0 + 4]);
            ah[mt][3] = __float_as_uint(sm[SM_AHI + (r0 + 8) * ASTR + c0 + 4]);
            al[mt][0] = __float_as_uint(sm[SM_ALO + r0 * ASTR + c0]);
            al[mt][1] = __float_as_uint(sm[SM_ALO + (r0 + 8) * ASTR + c0]);
            al[mt][2] = __float_as_uint(sm[SM_ALO + r0 * ASTR + c0 + 4]);
            al[mt][3] = __float_as_uint(sm[SM_ALO + (r0 + 8) * ASTR + c0 + 4]);
        }
#pragma unroll
        for (int nt = 0; nt < 8; nt++) {
            int ntg = warpN * 8 + nt;
            float4 b = *(const float4*)&sm[SM_BP + ((k8 * 16 + ntg) * 32 + lane) * 4];
            uint32_t bh[2] = { __float_as_uint(b.x), __float_as_uint(b.y) };
            uint32_t bl[2] = { __float_as_uint(b.z), __float_as_uint(b.w) };
#pragma unroll
            for (int mt = 0; mt < 2; mt++) {
                mma_tf32(acc[mt][nt], ah[mt], bh);
                mma_tf32(acc[mt][nt], ah[mt], bl);
                mma_tf32(acc[mt][nt], al[mt], bh);
            }
        }
    }
}

__device__ __forceinline__ void split_store_A(float* sm, float4 a, int arow, int f4) {
    float4 hi4, lo4;
    hi4.x = cvt_tf32(a.x); lo4.x = a.x - hi4.x;
    hi4.y = cvt_tf32(a.y); lo4.y = a.y - hi4.y;
    hi4.z = cvt_tf32(a.z); lo4.z = a.z - hi4.z;
    hi4.w = cvt_tf32(a.w); lo4.w = a.w - hi4.w;
    *(float4*)&sm[SM_AHI + arow * ASTR + f4 * 4] = hi4;
    *(float4*)&sm[SM_ALO + arow * ASTR + f4 * 4] = lo4;
}

// ---------------- degree histogram ----------------
__global__ void deg_kernel(const int* __restrict__ dst_pc, const int* __restrict__ dst_cp,
                           int* __restrict__ deg) {
    int i = blockIdx.x * blockDim.x + threadIdx.x;
    if (i < EE)               atomicAdd(&deg[NPAT + dst_pc[i]], 1);
    else if (i < 2 * EE)      atomicAdd(&deg[dst_cp[i - EE]], 1);
}

// ---------------- scan (+ rcnt + cur zero) ----------------
__global__ void scan_kernel(const int* __restrict__ deg, int* __restrict__ off,
                            float* __restrict__ rcnt, int* __restrict__ cur) {
    __shared__ int ssum[1024];
    int tid = threadIdx.x;
    const int PER = (NN + 1023) / 1024;
    int base = tid * PER;
    int s = 0;
    for (int i = 0; i < PER; i++) { int idx = base + i; if (idx < NN) s += deg[idx]; }
    ssum[tid] = s;
    __syncthreads();
    for (int ofs = 1; ofs < 1024; ofs <<= 1) {
        int v = (tid >= ofs) ? ssum[tid - ofs] : 0;
        __syncthreads();
        ssum[tid] += v;
        __syncthreads();
    }
    int run = (tid == 0) ? 0 : ssum[tid - 1];
    for (int i = 0; i < PER; i++) {
        int idx = base + i;
        if (idx < NN) {
            int d = deg[idx];
            off[idx] = run; run += d;
            rcnt[idx] = 1.0f / (float)max(d, 1);
            cur[idx] = 0;
        }
    }
    if (tid == 0) off[NN] = ssum[1023];
}

// ---------------- CSR fill ----------------
__global__ void fill_kernel(const int* __restrict__ src_pc, const int* __restrict__ dst_pc,
                            const int* __restrict__ src_cp, const int* __restrict__ dst_cp,
                            const int* __restrict__ off, int* __restrict__ cur,
                            int* __restrict__ csr) {
    int i = blockIdx.x * blockDim.x + threadIdx.x;
    int s, d;
    if (i < EE)          { s = src_pc[i];             d = NPAT + dst_pc[i]; }
    else if (i < 2 * EE) { s = NPAT + src_cp[i - EE]; d = dst_cp[i - EE]; }
    else return;
    int pos = off[d] + atomicAdd(&cur[d], 1);
    csr[pos] = s;
}

// ---------------- fp16 gather-aggregate ----------------
__global__ void gather_h_kernel(const __half* __restrict__ X16,
                                const int* __restrict__ off, const int* __restrict__ csr,
                                const float* __restrict__ rcnt, float* __restrict__ AGG) {
    int warp = (int)((blockIdx.x * (long long)blockDim.x + threadIdx.x) >> 5);
    if (warp >= NN) return;
    int lane = threadIdx.x & 31;
    int beg = off[warp], end = off[warp + 1];
    float4 acc = make_float4(0.f, 0.f, 0.f, 0.f);
    int e = beg;
    for (; e + 32 <= end; e += 32) {
        int idx = csr[e + lane];
#pragma unroll
        for (int j = 0; j < 32; j++) {
            int s = __shfl_sync(0xffffffffu, idx, j);
            uint2 u = ((const uint2*)(X16 + (size_t)s * HH))[lane];
            float2 f0 = __half22float2(*(__half2*)&u.x);
            float2 f1 = __half22float2(*(__half2*)&u.y);
            acc.x += f0.x; acc.y += f0.y; acc.z += f1.x; acc.w += f1.y;
        }
    }
    int rem = end - e;
    if (rem > 0) {
        int idx = (lane < rem) ? csr[e + lane] : 0;
        for (int j = 0; j < rem; j++) {
            int s = __shfl_sync(0xffffffffu, idx, j);
            uint2 u = ((const uint2*)(X16 + (size_t)s * HH))[lane];
            float2 f0 = __half22float2(*(__half2*)&u.x);
            float2 f1 = __half22float2(*(__half2*)&u.y);
            acc.x += f0.x; acc.y += f0.y; acc.z += f1.x; acc.w += f1.y;
        }
    }
    float rc = rcnt[warp];
    ((float4*)(AGG + (size_t)warp * HH))[lane] =
        make_float4(acc.x * rc, acc.y * rc, acc.z * rc, acc.w * rc);
}

// ---------------- weight prep: transpose + tf32-split + fragment-permute ------------
__global__ void prepB_kernel(const float* __restrict__ W_root, const float* __restrict__ W_rel,
                             const float* __restrict__ W_p, const float* __restrict__ W_c,
                             float* __restrict__ B) {
    int i = blockIdx.x * blockDim.x + threadIdx.x;
    float val; int k, n; int dstbase;
    if (i < 131072) {
        int v = i >> 15, rem = i & 32767;
        k = rem >> 7; n = rem & 127;
        int l = v >> 1, type = v & 1;
        if (k < 128) val = W_root[((size_t)l * 128 + k) * 128 + n];
        else {
            int rel = (type == 0) ? 1 : 0;
            val = W_rel[(((size_t)l * 2 + rel) * 128 + (k - 128)) * 128 + n];
        }
        dstbase = v * B_LAYER_V + (k >> 5) * B_CHUNK;
    } else if (i < 139264) {
        int rem = i - 131072; k = rem >> 7; n = rem & 127;
        val = W_p[k * 128 + n];
        dstbase = B_WP_OFF + (k >> 5) * B_CHUNK;
    } else if (i < 155648) {
        int rem = i - 139264; k = rem >> 7; n = rem & 127;
        val = W_c[k * 128 + n];
        dstbase = B_WC_OFF + (k >> 5) * B_CHUNK;
    } else return;
    int kin = k & 31, k8 = kin >> 3, p = kin & 7, tig = p & 3;
    int nt = n >> 3, gid = n & 7, lane = gid * 4 + tig;
    int slot = (p < 4) ? 0 : 1;
    float hi = cvt_tf32(val), lo = val - hi;
    int base = dstbase + ((k8 * 16 + nt) * 32 + lane) * 4;
    B[base + slot] = hi;
    B[base + slot + 2] = lo;
}

// ---------------- projection MMA: out = A[M,K] @ W + b (fp32 + fp16 copy) -----------
template <int KCH>
__global__ void __launch_bounds__(256, 2)
proj_mma_kernel(const float* __restrict__ A, const float* __restrict__ Bfrag,
                const float* __restrict__ bias, float* __restrict__ outF,
                __half* __restrict__ outH, int M, int rowOff) {
    extern __shared__ float sm[];
    int tid = threadIdx.x, wid = tid >> 5, lane = tid & 31;
    int warpM = wid & 3, warpN = wid >> 2;
    const int K = KCH * 32;

    float acc[2][8][4];
#pragma unroll
    for (int mt = 0; mt < 2; mt++)
#pragma unroll
        for (int nt = 0; nt < 8; nt++)
#pragma unroll
            for (int r = 0; r < 4; r++) acc[mt][nt][r] = 0.f;

    int arow = tid >> 1;
    int lr = blockIdx.x * 128 + arow;
    bool valid = lr < M;
    int f4base = (tid & 1) * 4;

#pragma unroll
    for (int chunk = 0; chunk < KCH; chunk++) {
        const float4* src4 = (const float4*)(A + (size_t)lr * K + chunk * 32);
#pragma unroll
        for (int i = 0; i < 4; i++) {
            int f4 = f4base + i;
            float4 a = valid ? src4[f4] : make_float4(0.f, 0.f, 0.f, 0.f);
            split_store_A(sm, a, arow, f4);
        }
        {
            const float4* bg = (const float4*)(Bfrag + (size_t)chunk * B_CHUNK);
            float4* sb = (float4*)&sm[SM_BP];
            for (int i = tid; i < 2048; i += 256) sb[i] = bg[i];
        }
        __syncthreads();
        chunk_mma(sm, warpM, warpN, lane, acc);
        __syncthreads();
    }

    int gid = lane >> 2, tig = lane & 3;
#pragma unroll
    for (int mt = 0; mt < 2; mt++) {
        int lrow = blockIdx.x * 128 + warpM * 32 + mt * 16 + gid;
#pragma unroll
        for (int nt = 0; nt < 8; nt++) {
            int col = warpN * 64 + nt * 8 + tig * 2;
            float2 bv = *(const float2*)&bias[col];
            if (lrow < M) {
                float2 o = make_float2(acc[mt][nt][0] + bv.x, acc[mt][nt][1] + bv.y);
                size_t gr = (size_t)(rowOff + lrow);
                *(float2*)&outF[gr * HH + col] = o;
                *(__half2*)&outH[gr * HH + col] = __floats2half2_rn(o.x, o.y);
            }
            if (lrow + 8 < M) {
                float2 o = make_float2(acc[mt][nt][2] + bv.x, acc[mt][nt][3] + bv.y);
                size_t gr = (size_t)(rowOff + lrow + 8);
                *(float2*)&outF[gr * HH + col] = o;
                *(__half2*)&outH[gr * HH + col] = __floats2half2_rn(o.x, o.y);
            }
        }
    }
}

// ---------------- layer MMA: out = relu([x|agg] @ Bv + b), fp32 (+ optional fp16) ---
__global__ void __launch_bounds__(256, 2)
layer_mma_kernel(const float* __restrict__ X, const float* __restrict__ AGG,
                 const float* __restrict__ Bpat, const float* __restrict__ Bcon,
                 const float* __restrict__ bias, float* __restrict__ outF,
                 __half* __restrict__ outH) {
    extern __shared__ float sm[];
    int tid = threadIdx.x, wid = tid >> 5, lane = tid & 31;
    int warpM = wid & 3, warpN = wid >> 2;

    const int NBP_T = (NPAT + 127) / 128;   // 391
    int bid = blockIdx.x;
    int base, rowlim;
    const float* Bfrag;
    if (bid < NBP_T) { base = bid * 128;                  rowlim = NPAT; Bfrag = Bpat; }
    else             { base = NPAT + (bid - NBP_T) * 128; rowlim = NN;   Bfrag = Bcon; }

    float acc[2][8][4];
#pragma unroll
    for (int mt = 0; mt < 2; mt++)
#pragma unroll
        for (int nt = 0; nt < 8; nt++)
#pragma unroll
            for (int r = 0; r < 4; r++) acc[mt][nt][r] = 0.f;

    int arow = tid >> 1;
    int node = base + arow;
    bool valid = node < rowlim;
    int f4base = (tid & 1) * 4;

#pragma unroll
    for (int chunk = 0; chunk < 8; chunk++) {
        const float4* src4 = (chunk < 4)
            ? (const float4*)(X   + (size_t)node * HH + chunk * 32)
            : (const float4*)(AGG + (size_t)node * HH + (chunk - 4) * 32);
#pragma unroll
        for (int i = 0; i < 4; i++) {
            int f4 = f4base + i;
            float4 a = valid ? src4[f4] : make_float4(0.f, 0.f, 0.f, 0.f);
            split_store_A(sm, a, arow, f4);
        }
        {
            const float4* bg = (const float4*)(Bfrag + (size_t)chunk * B_CHUNK);
            float4* sb = (float4*)&sm[SM_BP];
            for (int i = tid; i < 2048; i += 256) sb[i] = bg[i];
        }
        __syncthreads();
        chunk_mma(sm, warpM, warpN, lane, acc);
        __syncthreads();
    }

    int gid = lane >> 2, tig = lane & 3;
#pragma unroll
    for (int mt = 0; mt < 2; mt++) {
        int row = base + warpM * 32 + mt * 16 + gid;
#pragma unroll
        for (int nt = 0; nt < 8; nt++) {
            int col = warpN * 64 + nt * 8 + tig * 2;
            float2 bv = *(const float2*)&bias[col];
            if (row < rowlim) {
                float2 o;
                o.x = fmaxf(acc[mt][nt][0] + bv.x, 0.f);
                o.y = fmaxf(acc[mt][nt][1] + bv.y, 0.f);
                *(float2*)&outF[(size_t)row * HH + col] = o;
                if (outH) *(__half2*)&outH[(size_t)row * HH + col] = __floats2half2_rn(o.x, o.y);
            }
            if (row + 8 < rowlim) {
                float2 o;
                o.x = fmaxf(acc[mt][nt][2] + bv.x, 0.f);
                o.y = fmaxf(acc[mt][nt][3] + bv.y, 0.f);
                *(float2*)&outF[(size_t)(row + 8) * HH + col] = o;
                if (outH) *(__half2*)&outH[(size_t)(row + 8) * HH + col] = __floats2half2_rn(o.x, o.y);
            }
        }
    }
}

// ---------------- launch ----------------
extern "C" void kernel_launch(void* const* d_in, const int* in_sizes, int n_in,
                              void* d_out, int out_size) {
    const float* x_patient = (const float*)d_in[0];
    const float* x_concept = (const float*)d_in[1];
    const float* W_p    = (const float*)d_in[2];
    const float* b_p    = (const float*)d_in[3];
    const float* W_c    = (const float*)d_in[4];
    const float* b_c    = (const float*)d_in[5];
    const float* W_root = (const float*)d_in[6];
    const float* b_root = (const float*)d_in[7];
    const float* W_rel  = (const float*)d_in[8];
    const int* src_pc = (const int*)d_in[9];
    const int* dst_pc = (const int*)d_in[10];
    const int* src_cp = (const int*)d_in[11];
    const int* dst_cp = (const int*)d_in[12];
    float* out = (float*)d_out;

    float *buf0, *buf1, *agg, *rcnt, *Bg;
    __half *h0, *h1;
    int *deg, *off, *cur, *csr;
    cudaGetSymbolAddress((void**)&buf0, g_buf0);
    cudaGetSymbolAddress((void**)&buf1, g_buf1);
    cudaGetSymbolAddress((void**)&agg,  g_agg);
    cudaGetSymbolAddress((void**)&h0,   g_h0);
    cudaGetSymbolAddress((void**)&h1,   g_h1);
    cudaGetSymbolAddress((void**)&rcnt, g_rcnt);
    cudaGetSymbolAddress((void**)&deg,  g_deg);
    cudaGetSymbolAddress((void**)&off,  g_off);
    cudaGetSymbolAddress((void**)&cur,  g_cur);
    cudaGetSymbolAddress((void**)&csr,  g_csr);
    cudaGetSymbolAddress((void**)&Bg,   g_B);

    const int SMB = SM_FLOATS * 4;   // 69632 B
    cudaFuncSetAttribute(proj_mma_kernel<2>, cudaFuncAttributeMaxDynamicSharedMemorySize, SMB);
    cudaFuncSetAttribute(proj_mma_kernel<4>, cudaFuncAttributeMaxDynamicSharedMemorySize, SMB);
    cudaFuncSetAttribute(layer_mma_kernel,   cudaFuncAttributeMaxDynamicSharedMemorySize, SMB);

    // ---- CSR build ----
    cudaMemsetAsync(deg, 0, NN * sizeof(int));
    deg_kernel<<<(2 * EE + 255) / 256, 256>>>(dst_pc, dst_cp, deg);
    scan_kernel<<<1, 1024>>>(deg, off, rcnt, cur);
    fill_kernel<<<(2 * EE + 255) / 256, 256>>>(src_pc, dst_pc, src_cp, dst_cp, off, cur, csr);

    // ---- weight prep ----
    prepB_kernel<<<(155648 + 255) / 256, 256>>>(W_root, W_rel, W_p, W_c, Bg);

    // ---- projections (tensor path) ----
    proj_mma_kernel<2><<<(NPAT + 127) / 128, 256, SMB>>>(
        x_patient, Bg + B_WP_OFF, b_p, buf0, h0, NPAT, 0);
    proj_mma_kernel<4><<<(NCON + 127) / 128, 256, SMB>>>(
        x_concept, Bg + B_WC_OFF, b_c, buf0, h0, NCON, NPAT);

    const int NB_TC = (NPAT + 127) / 128 + (NCON + 127) / 128;  // 548
    const int GATHER_BLOCKS = (NN + 7) / 8;

    // ---- layer 0 ----
    gather_h_kernel<<<GATHER_BLOCKS, 256>>>(h0, off, csr, rcnt, agg);
    layer_mma_kernel<<<NB_TC, 256, SMB>>>(buf0, agg,
        Bg + 0 * B_LAYER_V, Bg + 1 * B_LAYER_V, b_root, buf1, h1);

    // ---- layer 1 ----
    gather_h_kernel<<<GATHER_BLOCKS, 256>>>(h1, off, csr, rcnt, agg);
    layer_mma_kernel<<<NB_TC, 256, SMB>>>(buf1, agg,
        Bg + 2 * B_LAYER_V, Bg + 3 * B_LAYER_V, b_root + HH, out, (__half*)nullptr);
}